// round 6
// baseline (speedup 1.0000x reference)
#include <cuda_runtime.h>

// dwtHaar_2d: x (8,64,512,512) f32 -> 4 subbands (8,64,256,256) concatenated.
// Reflect pad left/top by 1, stride 2, kernel 2 => non-overlapping windows.
// out[s][bc][i][j], s in {LL, LH, HL, HH}.
//
// R3: R1 structure (best measured; pure HBM-bound at ~86% DRAM) + __ldcs
// streaming loads (input is read exactly once -> evict-first keeps L2 for
// the write stream). 2 output cols per thread, 1 output row per block.

namespace {
constexpr int H  = 512;
constexpr int W  = 512;
constexpr int Ho = 256;
constexpr int Wo = 256;
constexpr int BC = 8 * 64;                         // 512
constexpr long long SUB = (long long)BC * Ho * Wo; // elements per subband
}

__global__ __launch_bounds__(128) void dwt_haar_kernel(
    const float* __restrict__ x, float* __restrict__ out)
{
    const int t  = threadIdx.x;      // 0..127 : handles output cols 2t, 2t+1
    const int i  = blockIdx.x;       // 0..255 : output row
    const int bc = blockIdx.y;       // 0..511

    const float* base = x + (size_t)bc * (H * W);
    const int r_top = (i == 0) ? 1 : (2 * i - 1);   // reflect row -1 -> row 1
    const int r_bot = 2 * i;

    const float* rowt = base + (size_t)r_top * W;
    const float* rowb = base + (size_t)r_bot * W;

    // Aligned 16B streaming loads: cols [4t .. 4t+3] of each row.
    const float4 vt = __ldcs(reinterpret_cast<const float4*>(rowt) + t);
    const float4 vb = __ldcs(reinterpret_cast<const float4*>(rowb) + t);

    // Left neighbor element (col 4t-1) via warp shuffle; fix up warp-edge lanes.
    float lt = __shfl_up_sync(0xffffffffu, vt.w, 1);
    float lb = __shfl_up_sync(0xffffffffu, vb.w, 1);
    if ((t & 31) == 0) {
        if (t == 0) {            // col -1 reflects to col 1
            lt = vt.y;
            lb = vb.y;
        } else {                 // cross-warp: one scalar load (L1/L2 hit)
            lt = __ldcs(rowt + 4 * t - 1);
            lb = __ldcs(rowb + 4 * t - 1);
        }
    }

    // Output col j0 = 2t: window cols (4t-1, 4t). Output col j1 = 2t+1: cols (4t+1, 4t+2).
    const float a0 = lt,   b0 = vt.x, c0 = lb,   d0 = vb.x;
    const float a1 = vt.y, b1 = vt.z, c1 = vb.y, d1 = vb.z;

    float2 ll, lh, hl, hh;
    ll.x = 0.5f * ( a0 + b0 + c0 + d0);
    ll.y = 0.5f * ( a1 + b1 + c1 + d1);
    lh.x = 0.5f * ( a0 + b0 - c0 - d0);
    lh.y = 0.5f * ( a1 + b1 - c1 - d1);
    hl.x = 0.5f * (-a0 + b0 - c0 + d0);
    hl.y = 0.5f * (-a1 + b1 - c1 + d1);
    hh.x = 0.5f * ( a0 - b0 - c0 + d0);
    hh.y = 0.5f * ( a1 - b1 - c1 + d1);

    const size_t obase = (size_t)bc * (Ho * Wo) + (size_t)i * Wo + 2 * t;
    *reinterpret_cast<float2*>(out + obase)           = ll;
    *reinterpret_cast<float2*>(out + SUB + obase)     = lh;
    *reinterpret_cast<float2*>(out + 2 * SUB + obase) = hl;
    *reinterpret_cast<float2*>(out + 3 * SUB + obase) = hh;
}

extern "C" void kernel_launch(void* const* d_in, const int* in_sizes, int n_in,
                              void* d_out, int out_size)
{
    const float* x = (const float*)d_in[0];
    float* out     = (float*)d_out;

    dim3 grid(Ho, BC);   // (256, 512)
    dim3 block(128);
    dwt_haar_kernel<<<grid, block>>>(x, out);
}

// round 8
// speedup vs baseline: 1.0631x; 1.0631x over previous
#include <cuda_runtime.h>

// dwtHaar_2d: x (8,64,512,512) f32 -> 4 subbands (8,64,256,256) concatenated.
// Reflect pad left/top by 1, stride 2, kernel 2 => non-overlapping windows.
// out[s][bc][i][j], s in {LL, LH, HL, HH}.
//
// R6: R1's exact per-thread memory pattern (plain LDG.128 x2, STG.64 x4 --
// cache hints measured as regressions), but 2 output rows per 256-thread
// block: halves CTA count, identical per-warp access pattern.

namespace {
constexpr int H  = 512;
constexpr int W  = 512;
constexpr int Ho = 256;
constexpr int Wo = 256;
constexpr int BC = 8 * 64;                         // 512
constexpr long long SUB = (long long)BC * Ho * Wo; // elements per subband
}

__global__ __launch_bounds__(256) void dwt_haar_kernel(
    const float* __restrict__ x, float* __restrict__ out)
{
    const int t    = threadIdx.x & 127;          // 0..127 : output cols 2t, 2t+1
    const int half = threadIdx.x >> 7;           // 0..1   : which output row
    const int i    = blockIdx.x * 2 + half;      // 0..255 : output row
    const int bc   = blockIdx.y;                 // 0..511

    const float* base = x + (size_t)bc * (H * W);
    const int r_top = (i == 0) ? 1 : (2 * i - 1);   // reflect row -1 -> row 1
    const int r_bot = 2 * i;

    const float* rowt = base + (size_t)r_top * W;
    const float* rowb = base + (size_t)r_bot * W;

    // Aligned 16B loads: cols [4t .. 4t+3] of each row.
    const float4 vt = reinterpret_cast<const float4*>(rowt)[t];
    const float4 vb = reinterpret_cast<const float4*>(rowb)[t];

    // Left neighbor element (col 4t-1) via warp shuffle; fix up warp-edge lanes.
    float lt = __shfl_up_sync(0xffffffffu, vt.w, 1);
    float lb = __shfl_up_sync(0xffffffffu, vb.w, 1);
    if ((t & 31) == 0) {
        if (t == 0) {            // col -1 reflects to col 1
            lt = vt.y;
            lb = vb.y;
        } else {                 // cross-warp: one scalar load (L1 hit)
            lt = rowt[4 * t - 1];
            lb = rowb[4 * t - 1];
        }
    }

    // Output col j0 = 2t: window cols (4t-1, 4t). Output col j1 = 2t+1: cols (4t+1, 4t+2).
    const float a0 = lt,   b0 = vt.x, c0 = lb,   d0 = vb.x;
    const float a1 = vt.y, b1 = vt.z, c1 = vb.y, d1 = vb.z;

    float2 ll, lh, hl, hh;
    ll.x = 0.5f * ( a0 + b0 + c0 + d0);
    ll.y = 0.5f * ( a1 + b1 + c1 + d1);
    lh.x = 0.5f * ( a0 + b0 - c0 - d0);
    lh.y = 0.5f * ( a1 + b1 - c1 - d1);
    hl.x = 0.5f * (-a0 + b0 - c0 + d0);
    hl.y = 0.5f * (-a1 + b1 - c1 + d1);
    hh.x = 0.5f * ( a0 - b0 - c0 + d0);
    hh.y = 0.5f * ( a1 - b1 - c1 + d1);

    const size_t obase = (size_t)bc * (Ho * Wo) + (size_t)i * Wo + 2 * t;
    *reinterpret_cast<float2*>(out + obase)           = ll;
    *reinterpret_cast<float2*>(out + SUB + obase)     = lh;
    *reinterpret_cast<float2*>(out + 2 * SUB + obase) = hl;
    *reinterpret_cast<float2*>(out + 3 * SUB + obase) = hh;
}

extern "C" void kernel_launch(void* const* d_in, const int* in_sizes, int n_in,
                              void* d_out, int out_size)
{
    const float* x = (const float*)d_in[0];
    float* out     = (float*)d_out;

    dim3 grid(Ho / 2, BC);   // (128, 512)
    dim3 block(256);
    dwt_haar_kernel<<<grid, block>>>(x, out);
}